// round 1
// baseline (speedup 1.0000x reference)
#include <cuda_runtime.h>
#include <cuda_bf16.h>
#include <math.h>

// ---------------- intermediate buffers (device globals; no allocation) ------
__device__ float g_a1[128 * 32 * 56 * 56];   // conv1 out  (51.4 MB)
__device__ float g_a2[128 * 64 * 28 * 28];   // conv2 out  (25.7 MB)
__device__ float g_a3[128 * 128 * 14 * 14];  // conv3 out  (12.8 MB)
__device__ float g_feat[128 * 512];          // pooled features

// ---------------- conv1: 3->32, 7x7, s4, p3, 224 -> 56 ----------------------
__global__ void conv1_kernel(const float* __restrict__ x, const float* __restrict__ w,
                             const float* __restrict__ cb, const float* __restrict__ bg,
                             const float* __restrict__ bb, const float* __restrict__ bm,
                             const float* __restrict__ bv) {
    __shared__ float ws[147 * 32];
    __shared__ float sc[32], sh[32];
    const int tid = threadIdx.x;
    const int b = blockIdx.y;

    for (int idx = tid; idx < 147 * 32; idx += 128) {
        int r = idx >> 5, oc = idx & 31;
        ws[idx] = w[oc * 147 + r];
    }
    if (tid < 32) {
        float s = bg[tid] * rsqrtf(bv[tid] + 1e-5f);
        sc[tid] = s;
        sh[tid] = (cb[tid] - bm[tid]) * s + bb[tid];
    }
    __syncthreads();

    int p = blockIdx.x * 128 + tid;
    if (p >= 56 * 56) return;
    int oh = p / 56, ow = p % 56;

    float acc[32];
#pragma unroll
    for (int i = 0; i < 32; i++) acc[i] = 0.f;

    const float* xb = x + (size_t)b * 3 * 224 * 224;
    for (int c = 0; c < 3; c++) {
#pragma unroll
        for (int kh = 0; kh < 7; kh++) {
            int ih = oh * 4 - 3 + kh;
            if (ih < 0 || ih >= 224) continue;
            const float* xr = xb + (c * 224 + ih) * 224;
            int rbase = (c * 7 + kh) * 7;
#pragma unroll
            for (int kw = 0; kw < 7; kw++) {
                int iw = ow * 4 - 3 + kw;
                if (iw < 0 || iw >= 224) continue;
                float xv = xr[iw];
                const float* wr = &ws[(rbase + kw) * 32];
#pragma unroll
                for (int oc = 0; oc < 32; oc++) acc[oc] = fmaf(xv, wr[oc], acc[oc]);
            }
        }
    }
    float* ob = g_a1 + ((size_t)b * 32) * 3136 + p;
#pragma unroll
    for (int oc = 0; oc < 32; oc++) {
        float y = acc[oc] * sc[oc] + sh[oc];
        ob[(size_t)oc * 3136] = fmaxf(y, 0.f);
    }
}

// ---------------- conv2: 32->64, 3x3, s2, p1, 56 -> 28 ----------------------
__global__ void conv2_kernel(const float* __restrict__ w,
                             const float* __restrict__ cb, const float* __restrict__ bg,
                             const float* __restrict__ bb, const float* __restrict__ bm,
                             const float* __restrict__ bv) {
    __shared__ float ws[288 * 32];  // 36.9 KB
    __shared__ float sc[32], sh[32];
    const int tid = threadIdx.x;
    const int b = blockIdx.y;
    const int ocb = blockIdx.z * 32;

    for (int idx = tid; idx < 288 * 32; idx += 128) {
        int r = idx >> 5, ocl = idx & 31;
        ws[idx] = w[(ocb + ocl) * 288 + r];
    }
    if (tid < 32) {
        int oc = ocb + tid;
        float s = bg[oc] * rsqrtf(bv[oc] + 1e-5f);
        sc[tid] = s;
        sh[tid] = (cb[oc] - bm[oc]) * s + bb[oc];
    }
    __syncthreads();

    int p = blockIdx.x * 128 + tid;
    if (p >= 28 * 28) return;
    int oh = p / 28, ow = p % 28;

    float acc[32];
#pragma unroll
    for (int i = 0; i < 32; i++) acc[i] = 0.f;

    const float* inb = g_a1 + (size_t)b * 32 * 3136;
    for (int ic = 0; ic < 32; ic++) {
        const float* ip = inb + (size_t)ic * 3136;
#pragma unroll
        for (int kh = 0; kh < 3; kh++) {
            int ih = oh * 2 - 1 + kh;
            if (ih < 0 || ih >= 56) continue;
#pragma unroll
            for (int kw = 0; kw < 3; kw++) {
                int iw = ow * 2 - 1 + kw;
                if (iw < 0 || iw >= 56) continue;
                float xv = ip[ih * 56 + iw];
                const float* wr = &ws[((ic * 3 + kh) * 3 + kw) * 32];
#pragma unroll
                for (int oc = 0; oc < 32; oc++) acc[oc] = fmaf(xv, wr[oc], acc[oc]);
            }
        }
    }
    float* ob = g_a2 + ((size_t)b * 64 + ocb) * 784 + p;
#pragma unroll
    for (int oc = 0; oc < 32; oc++) {
        float y = acc[oc] * sc[oc] + sh[oc];
        ob[(size_t)oc * 784] = fmaxf(y, 0.f);
    }
}

// ---------------- conv3: 64->128, 3x3, s2, p1, 28 -> 14 ---------------------
__global__ void conv3_kernel(const float* __restrict__ w,
                             const float* __restrict__ cb, const float* __restrict__ bg,
                             const float* __restrict__ bb, const float* __restrict__ bm,
                             const float* __restrict__ bv) {
    __shared__ float ws[576 * 16];  // 36.9 KB
    __shared__ float sc[16], sh[16];
    const int tid = threadIdx.x;
    const int b = blockIdx.x;
    const int ocb = blockIdx.y * 16;

    for (int idx = tid; idx < 576 * 16; idx += 224) {
        int r = idx >> 4, ocl = idx & 15;
        ws[idx] = w[(ocb + ocl) * 576 + r];
    }
    if (tid < 16) {
        int oc = ocb + tid;
        float s = bg[oc] * rsqrtf(bv[oc] + 1e-5f);
        sc[tid] = s;
        sh[tid] = (cb[oc] - bm[oc]) * s + bb[oc];
    }
    __syncthreads();

    int p = tid;
    if (p >= 14 * 14) return;
    int oh = p / 14, ow = p % 14;

    float acc[16];
#pragma unroll
    for (int i = 0; i < 16; i++) acc[i] = 0.f;

    const float* inb = g_a2 + (size_t)b * 64 * 784;
    for (int ic = 0; ic < 64; ic++) {
        const float* ip = inb + (size_t)ic * 784;
#pragma unroll
        for (int kh = 0; kh < 3; kh++) {
            int ih = oh * 2 - 1 + kh;
            if (ih < 0 || ih >= 28) continue;
#pragma unroll
            for (int kw = 0; kw < 3; kw++) {
                int iw = ow * 2 - 1 + kw;
                if (iw < 0 || iw >= 28) continue;
                float xv = ip[ih * 28 + iw];
                const float* wr = &ws[((ic * 3 + kh) * 3 + kw) * 16];
#pragma unroll
                for (int oc = 0; oc < 16; oc++) acc[oc] = fmaf(xv, wr[oc], acc[oc]);
            }
        }
    }
    float* ob = g_a3 + ((size_t)b * 128 + ocb) * 196 + p;
#pragma unroll
    for (int oc = 0; oc < 16; oc++) {
        float y = acc[oc] * sc[oc] + sh[oc];
        ob[(size_t)oc * 196] = fmaxf(y, 0.f);
    }
}

// ---------------- adaptive avgpool (2,2): 14x14 -> 2x2 ----------------------
__global__ void pool_kernel() {
    int idx = blockIdx.x * 256 + threadIdx.x;
    if (idx >= 128 * 512) return;
    int b = idx >> 9;
    int r = idx & 511;
    int c = r >> 2;
    int ph = (r >> 1) & 1;
    int pw = r & 1;
    const float* src = g_a3 + (((size_t)b * 128 + c) * 14 + ph * 7) * 14 + pw * 7;
    float s = 0.f;
#pragma unroll
    for (int h = 0; h < 7; h++)
#pragma unroll
        for (int w = 0; w < 7; w++) s += src[h * 14 + w];
    g_feat[idx] = s * (1.f / 49.f);
}

// ---------------- head: linear->tanh, quantum circuit, MLP ------------------
__global__ void head_kernel(const float* __restrict__ pre_w, const float* __restrict__ pre_b,
                            const float* __restrict__ qw,
                            const float* __restrict__ pw1, const float* __restrict__ pb1,
                            const float* __restrict__ pw2, const float* __restrict__ pb2,
                            float* __restrict__ out) {
    __shared__ float f_s[512];
    __shared__ float ang_s[4], q_s[4], h1_s[64];
    const int tid = threadIdx.x;
    const int b = blockIdx.x;

    for (int i = tid; i < 512; i += 128) f_s[i] = g_feat[b * 512 + i];
    __syncthreads();

    // 4 warps, each computes one angle (512-dot + tanh * pi)
    int wid = tid >> 5, lane = tid & 31;
    {
        float partial = 0.f;
        const float* wr = pre_w + wid * 512;
        for (int k = lane; k < 512; k += 32) partial += f_s[k] * wr[k];
#pragma unroll
        for (int o = 16; o > 0; o >>= 1) partial += __shfl_down_sync(0xffffffffu, partial, o);
        if (lane == 0) ang_s[wid] = tanhf(partial + pre_b[wid]) * 3.14159265358979323846f;
    }
    __syncthreads();

    // 4-qubit statevector simulation (wire 0 = MSB), thread 0 only
    if (tid == 0) {
        float sr[16], si[16];
        float cq[4], sq[4];
#pragma unroll
        for (int q = 0; q < 4; q++) {
            cq[q] = cosf(0.5f * ang_s[q]);
            sq[q] = sinf(0.5f * ang_s[q]);
        }
#pragma unroll
        for (int i = 0; i < 16; i++) {
            float vv = 1.f;
#pragma unroll
            for (int q = 0; q < 4; q++) vv *= ((i >> (3 - q)) & 1) ? sq[q] : cq[q];
            sr[i] = vv;
            si[i] = 0.f;
        }
        for (int l = 0; l < 2; l++) {
            for (int q = 0; q < 4; q++) {
                const int mk = 1 << (3 - q);
                const float* qwp = qw + (l * 4 + q) * 3;
                float c, s;
                // RX
                c = cosf(0.5f * qwp[0]); s = sinf(0.5f * qwp[0]);
                for (int i = 0; i < 16; i++)
                    if (!(i & mk)) {
                        int j = i | mk;
                        float r0 = sr[i], i0 = si[i], r1 = sr[j], i1 = si[j];
                        sr[i] = c * r0 + s * i1;  si[i] = c * i0 - s * r1;
                        sr[j] = c * r1 + s * i0;  si[j] = c * i1 - s * r0;
                    }
                // RY
                c = cosf(0.5f * qwp[1]); s = sinf(0.5f * qwp[1]);
                for (int i = 0; i < 16; i++)
                    if (!(i & mk)) {
                        int j = i | mk;
                        float r0 = sr[i], i0 = si[i], r1 = sr[j], i1 = si[j];
                        sr[i] = c * r0 - s * r1;  si[i] = c * i0 - s * i1;
                        sr[j] = s * r0 + c * r1;  si[j] = s * i0 + c * i1;
                    }
                // RZ
                c = cosf(0.5f * qwp[2]); s = sinf(0.5f * qwp[2]);
                for (int i = 0; i < 16; i++) {
                    float r = sr[i], im = si[i];
                    if (i & mk) { sr[i] = c * r - s * im; si[i] = c * im + s * r; }
                    else        { sr[i] = c * r + s * im; si[i] = c * im - s * r; }
                }
            }
            // ring CNOTs: (0,1),(1,2),(2,3),(3,0) — swap pairs where control=1
            for (int e = 0; e < 4; e++) {
                int cm = 1 << (3 - e);
                int tm = 1 << (3 - ((e + 1) & 3));
                for (int i = 0; i < 16; i++)
                    if ((i & cm) && !(i & tm)) {
                        int j = i | tm;
                        float t = sr[i]; sr[i] = sr[j]; sr[j] = t;
                        t = si[i]; si[i] = si[j]; si[j] = t;
                    }
            }
        }
        for (int q = 0; q < 4; q++) {
            float z = 0.f;
            for (int i = 0; i < 16; i++) {
                float pp = sr[i] * sr[i] + si[i] * si[i];
                z += ((i >> (3 - q)) & 1) ? -pp : pp;
            }
            q_s[q] = z;
        }
    }
    __syncthreads();

    if (tid < 64) {
        float h = pb1[tid];
#pragma unroll
        for (int j = 0; j < 4; j++) h += q_s[j] * pw1[tid * 4 + j];
        h1_s[tid] = fmaxf(h, 0.f);
    }
    __syncthreads();

    if (tid < 5) {
        float o = pb2[tid];
        for (int k = 0; k < 64; k++) o += h1_s[k] * pw2[tid * 64 + k];
        out[b * 5 + tid] = o;
    }
}

// ---------------- launch ----------------------------------------------------
extern "C" void kernel_launch(void* const* d_in, const int* in_sizes, int n_in,
                              void* d_out, int out_size) {
    const float* x    = (const float*)d_in[0];
    const float* c1w  = (const float*)d_in[1];
    const float* c1b  = (const float*)d_in[2];
    const float* bn1g = (const float*)d_in[3];
    const float* bn1b = (const float*)d_in[4];
    const float* bn1m = (const float*)d_in[5];
    const float* bn1v = (const float*)d_in[6];
    const float* c2w  = (const float*)d_in[7];
    const float* c2b  = (const float*)d_in[8];
    const float* bn2g = (const float*)d_in[9];
    const float* bn2b = (const float*)d_in[10];
    const float* bn2m = (const float*)d_in[11];
    const float* bn2v = (const float*)d_in[12];
    const float* c3w  = (const float*)d_in[13];
    const float* c3b  = (const float*)d_in[14];
    const float* bn3g = (const float*)d_in[15];
    const float* bn3b = (const float*)d_in[16];
    const float* bn3m = (const float*)d_in[17];
    const float* bn3v = (const float*)d_in[18];
    const float* pre_w = (const float*)d_in[19];
    const float* pre_b = (const float*)d_in[20];
    const float* qw    = (const float*)d_in[21];
    const float* pw1   = (const float*)d_in[22];
    const float* pb1   = (const float*)d_in[23];
    const float* pw2   = (const float*)d_in[24];
    const float* pb2   = (const float*)d_in[25];
    float* out = (float*)d_out;

    conv1_kernel<<<dim3(25, 128), 128>>>(x, c1w, c1b, bn1g, bn1b, bn1m, bn1v);
    conv2_kernel<<<dim3(7, 128, 2), 128>>>(c2w, c2b, bn2g, bn2b, bn2m, bn2v);
    conv3_kernel<<<dim3(128, 8), 224>>>(c3w, c3b, bn3g, bn3b, bn3m, bn3v);
    pool_kernel<<<256, 256>>>();
    head_kernel<<<128, 128>>>(pre_w, pre_b, qw, pw1, pb1, pw2, pb2, out);
}

// round 2
// speedup vs baseline: 1.0931x; 1.0931x over previous
#include <cuda_runtime.h>
#include <cuda_bf16.h>
#include <math.h>

// ---------------- intermediate buffers (device globals; no allocation) ------
__device__ float g_a1[128 * 32 * 56 * 56];   // conv1 out  (51.4 MB)
__device__ float g_a2[128 * 64 * 28 * 28];   // conv2 out  (25.7 MB)
__device__ float g_a3[128 * 128 * 14 * 14];  // conv3 out  (12.8 MB)
__device__ float g_feat[128 * 512];          // pooled features

// packed f32x2 helpers -------------------------------------------------------
#define FMA2(acc, a, b) \
    asm("fma.rn.f32x2 %0, %1, %2, %0;" : "+l"(acc) : "l"(a), "l"(b))

__device__ __forceinline__ unsigned long long bcast2(float v) {
    unsigned long long r;
    asm("mov.b64 %0, {%1, %1};" : "=l"(r) : "r"(__float_as_uint(v)));
    return r;
}
__device__ __forceinline__ unsigned long long packf2(float lo, float hi) {
    return (unsigned long long)__float_as_uint(lo) |
           ((unsigned long long)__float_as_uint(hi) << 32);
}
__device__ __forceinline__ void unpack2(unsigned long long v, float& lo, float& hi) {
    unsigned int a, b;
    asm("mov.b64 {%0, %1}, %2;" : "=r"(a), "=r"(b) : "l"(v));
    lo = __uint_as_float(a);
    hi = __uint_as_float(b);
}

// ---------------- conv1: 3->32, 7x7, s4, p3, 224 -> 56 ----------------------
__global__ void conv1_kernel(const float* __restrict__ x, const float* __restrict__ w,
                             const float* __restrict__ cb, const float* __restrict__ bg,
                             const float* __restrict__ bb, const float* __restrict__ bm,
                             const float* __restrict__ bv) {
    __shared__ __align__(16) unsigned long long ws2[147 * 16];  // packed oc-pairs
    __shared__ float sc[32], sh[32];
    const int tid = threadIdx.x;
    const int b = blockIdx.y;

    for (int idx = tid; idx < 147 * 16; idx += 128) {
        int r = idx >> 4, ocp = idx & 15;
        ws2[idx] = packf2(w[(2 * ocp) * 147 + r], w[(2 * ocp + 1) * 147 + r]);
    }
    if (tid < 32) {
        float s = bg[tid] * rsqrtf(bv[tid] + 1e-5f);
        sc[tid] = s;
        sh[tid] = (cb[tid] - bm[tid]) * s + bb[tid];
    }
    __syncthreads();

    int p = blockIdx.x * 128 + tid;
    if (p >= 56 * 56) return;
    int oh = p / 56, ow = p % 56;

    unsigned long long acc[16];
#pragma unroll
    for (int i = 0; i < 16; i++) acc[i] = 0ull;

    const float* xb = x + (size_t)b * 3 * 224 * 224;
    for (int c = 0; c < 3; c++) {
#pragma unroll
        for (int kh = 0; kh < 7; kh++) {
            int ih = oh * 4 - 3 + kh;
            if (ih < 0 || ih >= 224) continue;
            const float* xr = xb + (c * 224 + ih) * 224;
            int rbase = (c * 7 + kh) * 7;
#pragma unroll
            for (int kw = 0; kw < 7; kw++) {
                int iw = ow * 4 - 3 + kw;
                if (iw < 0 || iw >= 224) continue;
                unsigned long long x2 = bcast2(xr[iw]);
                const ulonglong2* wp =
                    reinterpret_cast<const ulonglong2*>(&ws2[(rbase + kw) * 16]);
#pragma unroll
                for (int i = 0; i < 8; i++) {
                    ulonglong2 wv = wp[i];
                    FMA2(acc[2 * i],     x2, wv.x);
                    FMA2(acc[2 * i + 1], x2, wv.y);
                }
            }
        }
    }
    float* ob = g_a1 + ((size_t)b * 32) * 3136 + p;
#pragma unroll
    for (int i = 0; i < 16; i++) {
        float y0, y1;
        unpack2(acc[i], y0, y1);
        int oc = 2 * i;
        ob[(size_t)oc * 3136]       = fmaxf(y0 * sc[oc] + sh[oc], 0.f);
        ob[(size_t)(oc + 1) * 3136] = fmaxf(y1 * sc[oc + 1] + sh[oc + 1], 0.f);
    }
}

// ---------------- conv2: 32->64, 3x3, s2, p1, 56 -> 28 ----------------------
__global__ void conv2_kernel(const float* __restrict__ w,
                             const float* __restrict__ cb, const float* __restrict__ bg,
                             const float* __restrict__ bb, const float* __restrict__ bm,
                             const float* __restrict__ bv) {
    __shared__ __align__(16) unsigned long long ws2[288 * 16];  // 36.9 KB
    __shared__ float sc[32], sh[32];
    const int tid = threadIdx.x;
    const int b = blockIdx.y;
    const int ocb = blockIdx.z * 32;

    for (int idx = tid; idx < 288 * 16; idx += 128) {
        int r = idx >> 4, ocp = idx & 15;
        ws2[idx] = packf2(w[(ocb + 2 * ocp) * 288 + r],
                          w[(ocb + 2 * ocp + 1) * 288 + r]);
    }
    if (tid < 32) {
        int oc = ocb + tid;
        float s = bg[oc] * rsqrtf(bv[oc] + 1e-5f);
        sc[tid] = s;
        sh[tid] = (cb[oc] - bm[oc]) * s + bb[oc];
    }
    __syncthreads();

    int p = blockIdx.x * 128 + tid;
    if (p >= 28 * 28) return;
    int oh = p / 28, ow = p % 28;

    unsigned long long acc[16];
#pragma unroll
    for (int i = 0; i < 16; i++) acc[i] = 0ull;

    const float* inb = g_a1 + (size_t)b * 32 * 3136;
    for (int ic = 0; ic < 32; ic++) {
        const float* ip = inb + (size_t)ic * 3136;
#pragma unroll
        for (int kh = 0; kh < 3; kh++) {
            int ih = oh * 2 - 1 + kh;
            if (ih < 0 || ih >= 56) continue;
#pragma unroll
            for (int kw = 0; kw < 3; kw++) {
                int iw = ow * 2 - 1 + kw;
                if (iw < 0 || iw >= 56) continue;
                unsigned long long x2 = bcast2(__ldg(ip + ih * 56 + iw));
                const ulonglong2* wp = reinterpret_cast<const ulonglong2*>(
                    &ws2[((ic * 3 + kh) * 3 + kw) * 16]);
#pragma unroll
                for (int i = 0; i < 8; i++) {
                    ulonglong2 wv = wp[i];
                    FMA2(acc[2 * i],     x2, wv.x);
                    FMA2(acc[2 * i + 1], x2, wv.y);
                }
            }
        }
    }
    float* ob = g_a2 + ((size_t)b * 64 + ocb) * 784 + p;
#pragma unroll
    for (int i = 0; i < 16; i++) {
        float y0, y1;
        unpack2(acc[i], y0, y1);
        int oc = 2 * i;
        ob[(size_t)oc * 784]       = fmaxf(y0 * sc[oc] + sh[oc], 0.f);
        ob[(size_t)(oc + 1) * 784] = fmaxf(y1 * sc[oc + 1] + sh[oc + 1], 0.f);
    }
}

// ---------------- conv3: 64->128, 3x3, s2, p1, 28 -> 14 ---------------------
__global__ void conv3_kernel(const float* __restrict__ w,
                             const float* __restrict__ cb, const float* __restrict__ bg,
                             const float* __restrict__ bb, const float* __restrict__ bm,
                             const float* __restrict__ bv) {
    __shared__ __align__(16) unsigned long long ws2[576 * 8];  // 36.9 KB
    __shared__ float sc[16], sh[16];
    const int tid = threadIdx.x;
    const int b = blockIdx.x;
    const int ocb = blockIdx.y * 16;

    for (int idx = tid; idx < 576 * 8; idx += 224) {
        int r = idx >> 3, ocp = idx & 7;
        ws2[idx] = packf2(w[(ocb + 2 * ocp) * 576 + r],
                          w[(ocb + 2 * ocp + 1) * 576 + r]);
    }
    if (tid < 16) {
        int oc = ocb + tid;
        float s = bg[oc] * rsqrtf(bv[oc] + 1e-5f);
        sc[tid] = s;
        sh[tid] = (cb[oc] - bm[oc]) * s + bb[oc];
    }
    __syncthreads();

    int p = tid;
    if (p >= 14 * 14) return;
    int oh = p / 14, ow = p % 14;

    unsigned long long acc[8];
#pragma unroll
    for (int i = 0; i < 8; i++) acc[i] = 0ull;

    const float* inb = g_a2 + (size_t)b * 64 * 784;
    for (int ic = 0; ic < 64; ic++) {
        const float* ip = inb + (size_t)ic * 784;
#pragma unroll
        for (int kh = 0; kh < 3; kh++) {
            int ih = oh * 2 - 1 + kh;
            if (ih < 0 || ih >= 28) continue;
#pragma unroll
            for (int kw = 0; kw < 3; kw++) {
                int iw = ow * 2 - 1 + kw;
                if (iw < 0 || iw >= 28) continue;
                unsigned long long x2 = bcast2(__ldg(ip + ih * 28 + iw));
                const ulonglong2* wp = reinterpret_cast<const ulonglong2*>(
                    &ws2[((ic * 3 + kh) * 3 + kw) * 8]);
#pragma unroll
                for (int i = 0; i < 4; i++) {
                    ulonglong2 wv = wp[i];
                    FMA2(acc[2 * i],     x2, wv.x);
                    FMA2(acc[2 * i + 1], x2, wv.y);
                }
            }
        }
    }
    float* ob = g_a3 + ((size_t)b * 128 + ocb) * 196 + p;
#pragma unroll
    for (int i = 0; i < 8; i++) {
        float y0, y1;
        unpack2(acc[i], y0, y1);
        int oc = 2 * i;
        ob[(size_t)oc * 196]       = fmaxf(y0 * sc[oc] + sh[oc], 0.f);
        ob[(size_t)(oc + 1) * 196] = fmaxf(y1 * sc[oc + 1] + sh[oc + 1], 0.f);
    }
}

// ---------------- adaptive avgpool (2,2): 14x14 -> 2x2 ----------------------
__global__ void pool_kernel() {
    int idx = blockIdx.x * 256 + threadIdx.x;
    if (idx >= 128 * 512) return;
    int b = idx >> 9;
    int r = idx & 511;
    int c = r >> 2;
    int ph = (r >> 1) & 1;
    int pw = r & 1;
    const float* src = g_a3 + (((size_t)b * 128 + c) * 14 + ph * 7) * 14 + pw * 7;
    float s = 0.f;
#pragma unroll
    for (int h = 0; h < 7; h++)
#pragma unroll
        for (int w = 0; w < 7; w++) s += src[h * 14 + w];
    g_feat[idx] = s * (1.f / 49.f);
}

// ---------------- head: linear->tanh, quantum circuit, MLP ------------------
__global__ void head_kernel(const float* __restrict__ pre_w, const float* __restrict__ pre_b,
                            const float* __restrict__ qw,
                            const float* __restrict__ pw1, const float* __restrict__ pb1,
                            const float* __restrict__ pw2, const float* __restrict__ pb2,
                            float* __restrict__ out) {
    __shared__ float f_s[512];
    __shared__ float ang_s[4], q_s[4], h1_s[64];
    const int tid = threadIdx.x;
    const int b = blockIdx.x;

    for (int i = tid; i < 512; i += 128) f_s[i] = g_feat[b * 512 + i];
    __syncthreads();

    int wid = tid >> 5, lane = tid & 31;
    {
        float partial = 0.f;
        const float* wr = pre_w + wid * 512;
        for (int k = lane; k < 512; k += 32) partial += f_s[k] * wr[k];
#pragma unroll
        for (int o = 16; o > 0; o >>= 1) partial += __shfl_down_sync(0xffffffffu, partial, o);
        if (lane == 0) ang_s[wid] = tanhf(partial + pre_b[wid]) * 3.14159265358979323846f;
    }
    __syncthreads();

    if (tid == 0) {
        float sr[16], si[16];
        float cq[4], sq[4];
#pragma unroll
        for (int q = 0; q < 4; q++) {
            cq[q] = cosf(0.5f * ang_s[q]);
            sq[q] = sinf(0.5f * ang_s[q]);
        }
#pragma unroll
        for (int i = 0; i < 16; i++) {
            float vv = 1.f;
#pragma unroll
            for (int q = 0; q < 4; q++) vv *= ((i >> (3 - q)) & 1) ? sq[q] : cq[q];
            sr[i] = vv;
            si[i] = 0.f;
        }
        for (int l = 0; l < 2; l++) {
            for (int q = 0; q < 4; q++) {
                const int mk = 1 << (3 - q);
                const float* qwp = qw + (l * 4 + q) * 3;
                float c, s;
                c = cosf(0.5f * qwp[0]); s = sinf(0.5f * qwp[0]);
                for (int i = 0; i < 16; i++)
                    if (!(i & mk)) {
                        int j = i | mk;
                        float r0 = sr[i], i0 = si[i], r1 = sr[j], i1 = si[j];
                        sr[i] = c * r0 + s * i1;  si[i] = c * i0 - s * r1;
                        sr[j] = c * r1 + s * i0;  si[j] = c * i1 - s * r0;
                    }
                c = cosf(0.5f * qwp[1]); s = sinf(0.5f * qwp[1]);
                for (int i = 0; i < 16; i++)
                    if (!(i & mk)) {
                        int j = i | mk;
                        float r0 = sr[i], i0 = si[i], r1 = sr[j], i1 = si[j];
                        sr[i] = c * r0 - s * r1;  si[i] = c * i0 - s * i1;
                        sr[j] = s * r0 + c * r1;  si[j] = s * i0 + c * i1;
                    }
                c = cosf(0.5f * qwp[2]); s = sinf(0.5f * qwp[2]);
                for (int i = 0; i < 16; i++) {
                    float r = sr[i], im = si[i];
                    if (i & mk) { sr[i] = c * r - s * im; si[i] = c * im + s * r; }
                    else        { sr[i] = c * r + s * im; si[i] = c * im - s * r; }
                }
            }
            for (int e = 0; e < 4; e++) {
                int cm = 1 << (3 - e);
                int tm = 1 << (3 - ((e + 1) & 3));
                for (int i = 0; i < 16; i++)
                    if ((i & cm) && !(i & tm)) {
                        int j = i | tm;
                        float t = sr[i]; sr[i] = sr[j]; sr[j] = t;
                        t = si[i]; si[i] = si[j]; si[j] = t;
                    }
            }
        }
        for (int q = 0; q < 4; q++) {
            float z = 0.f;
            for (int i = 0; i < 16; i++) {
                float pp = sr[i] * sr[i] + si[i] * si[i];
                z += ((i >> (3 - q)) & 1) ? -pp : pp;
            }
            q_s[q] = z;
        }
    }
    __syncthreads();

    if (tid < 64) {
        float h = pb1[tid];
#pragma unroll
        for (int j = 0; j < 4; j++) h += q_s[j] * pw1[tid * 4 + j];
        h1_s[tid] = fmaxf(h, 0.f);
    }
    __syncthreads();

    if (tid < 5) {
        float o = pb2[tid];
        for (int k = 0; k < 64; k++) o += h1_s[k] * pw2[tid * 64 + k];
        out[b * 5 + tid] = o;
    }
}

// ---------------- launch ----------------------------------------------------
extern "C" void kernel_launch(void* const* d_in, const int* in_sizes, int n_in,
                              void* d_out, int out_size) {
    const float* x    = (const float*)d_in[0];
    const float* c1w  = (const float*)d_in[1];
    const float* c1b  = (const float*)d_in[2];
    const float* bn1g = (const float*)d_in[3];
    const float* bn1b = (const float*)d_in[4];
    const float* bn1m = (const float*)d_in[5];
    const float* bn1v = (const float*)d_in[6];
    const float* c2w  = (const float*)d_in[7];
    const float* c2b  = (const float*)d_in[8];
    const float* bn2g = (const float*)d_in[9];
    const float* bn2b = (const float*)d_in[10];
    const float* bn2m = (const float*)d_in[11];
    const float* bn2v = (const float*)d_in[12];
    const float* c3w  = (const float*)d_in[13];
    const float* c3b  = (const float*)d_in[14];
    const float* bn3g = (const float*)d_in[15];
    const float* bn3b = (const float*)d_in[16];
    const float* bn3m = (const float*)d_in[17];
    const float* bn3v = (const float*)d_in[18];
    const float* pre_w = (const float*)d_in[19];
    const float* pre_b = (const float*)d_in[20];
    const float* qw    = (const float*)d_in[21];
    const float* pw1   = (const float*)d_in[22];
    const float* pb1   = (const float*)d_in[23];
    const float* pw2   = (const float*)d_in[24];
    const float* pb2   = (const float*)d_in[25];
    float* out = (float*)d_out;

    conv1_kernel<<<dim3(25, 128), 128>>>(x, c1w, c1b, bn1g, bn1b, bn1m, bn1v);
    conv2_kernel<<<dim3(7, 128, 2), 128>>>(c2w, c2b, bn2g, bn2b, bn2m, bn2v);
    conv3_kernel<<<dim3(128, 8), 224>>>(c3w, c3b, bn3g, bn3b, bn3m, bn3v);
    pool_kernel<<<256, 256>>>();
    head_kernel<<<128, 128>>>(pre_w, pre_b, qw, pw1, pb1, pw2, pb2, out);
}

// round 3
// speedup vs baseline: 1.2652x; 1.1575x over previous
#include <cuda_runtime.h>
#include <cuda_bf16.h>
#include <math.h>

// ---------------- intermediate buffers (device globals; no allocation) ------
__device__ float g_a1[128 * 32 * 56 * 56];   // conv1 out
__device__ float g_a2[128 * 64 * 28 * 28];   // conv2 out
__device__ float g_a3[128 * 128 * 14 * 14];  // conv3 out
__device__ float g_feat[128 * 512];          // pooled features

// packed f32x2 helpers -------------------------------------------------------
#define FMA2(acc, a, b) \
    asm("fma.rn.f32x2 %0, %1, %2, %0;" : "+l"(acc) : "l"(a), "l"(b))

__device__ __forceinline__ unsigned long long bcast2(float v) {
    unsigned long long r;
    asm("mov.b64 %0, {%1, %1};" : "=l"(r) : "r"(__float_as_uint(v)));
    return r;
}
__device__ __forceinline__ unsigned long long packf2(float lo, float hi) {
    return (unsigned long long)__float_as_uint(lo) |
           ((unsigned long long)__float_as_uint(hi) << 32);
}
__device__ __forceinline__ void unpack2(unsigned long long v, float& lo, float& hi) {
    unsigned int a, b;
    asm("mov.b64 {%0, %1}, %2;" : "=r"(a), "=r"(b) : "l"(v));
    lo = __uint_as_float(a);
    hi = __uint_as_float(b);
}

// ---------------- conv1: 3->32, 7x7, s4, p3, 224 -> 56, 2 px/thread ---------
__global__ void conv1_kernel(const float* __restrict__ x, const float* __restrict__ w,
                             const float* __restrict__ cb, const float* __restrict__ bg,
                             const float* __restrict__ bb, const float* __restrict__ bm,
                             const float* __restrict__ bv) {
    __shared__ __align__(16) unsigned long long ws2[147 * 16];
    __shared__ float sc[32], sh[32];
    const int tid = threadIdx.x;
    const int b = blockIdx.y;

    for (int idx = tid; idx < 147 * 16; idx += 128) {
        int r = idx >> 4, ocp = idx & 15;
        ws2[idx] = packf2(w[(2 * ocp) * 147 + r], w[(2 * ocp + 1) * 147 + r]);
    }
    if (tid < 32) {
        float s = bg[tid] * rsqrtf(bv[tid] + 1e-5f);
        sc[tid] = s;
        sh[tid] = (cb[tid] - bm[tid]) * s + bb[tid];
    }
    __syncthreads();

    int p0 = blockIdx.x * 256 + tid;
    if (p0 >= 56 * 56) return;
    int p1 = p0 + 128;
    bool v1 = (p1 < 56 * 56);
    if (!v1) p1 = p0;  // duplicate work, skip store

    int oh0 = p0 / 56, ow0 = p0 % 56;
    int oh1 = p1 / 56, ow1 = p1 % 56;

    unsigned long long a0[16], a1[16];
#pragma unroll
    for (int i = 0; i < 16; i++) { a0[i] = 0ull; a1[i] = 0ull; }

    const float* xb = x + (size_t)b * 3 * 224 * 224;
    for (int c = 0; c < 3; c++) {
        for (int kh = 0; kh < 7; kh++) {
            int ih0 = oh0 * 4 - 3 + kh;
            int ih1 = oh1 * 4 - 3 + kh;
            bool r0 = (unsigned)ih0 < 224u;
            bool r1 = (unsigned)ih1 < 224u;
            const float* xr0 = xb + (c * 224 + ih0) * 224;
            const float* xr1 = xb + (c * 224 + ih1) * 224;
            int rbase = (c * 7 + kh) * 7;
#pragma unroll
            for (int kw = 0; kw < 7; kw++) {
                int iw0 = ow0 * 4 - 3 + kw;
                int iw1 = ow1 * 4 - 3 + kw;
                float xv0 = (r0 && (unsigned)iw0 < 224u) ? __ldg(xr0 + iw0) : 0.f;
                float xv1 = (r1 && (unsigned)iw1 < 224u) ? __ldg(xr1 + iw1) : 0.f;
                unsigned long long x20 = bcast2(xv0), x21 = bcast2(xv1);
                const ulonglong2* wp =
                    reinterpret_cast<const ulonglong2*>(&ws2[(rbase + kw) * 16]);
#pragma unroll
                for (int i = 0; i < 8; i++) {
                    ulonglong2 wv = wp[i];
                    FMA2(a0[2 * i],     x20, wv.x);
                    FMA2(a0[2 * i + 1], x20, wv.y);
                    FMA2(a1[2 * i],     x21, wv.x);
                    FMA2(a1[2 * i + 1], x21, wv.y);
                }
            }
        }
    }
    float* ob = g_a1 + (size_t)b * 32 * 3136;
#pragma unroll
    for (int i = 0; i < 16; i++) {
        float y0, y1, z0, z1;
        unpack2(a0[i], y0, y1);
        unpack2(a1[i], z0, z1);
        int oc = 2 * i;
        ob[(size_t)oc * 3136 + p0]       = fmaxf(y0 * sc[oc] + sh[oc], 0.f);
        ob[(size_t)(oc + 1) * 3136 + p0] = fmaxf(y1 * sc[oc + 1] + sh[oc + 1], 0.f);
        if (v1) {
            ob[(size_t)oc * 3136 + p1]       = fmaxf(z0 * sc[oc] + sh[oc], 0.f);
            ob[(size_t)(oc + 1) * 3136 + p1] = fmaxf(z1 * sc[oc + 1] + sh[oc + 1], 0.f);
        }
    }
}

// ---------------- conv2: 32->64, 3x3, s2, p1, 56 -> 28, 2 px/thread ---------
__global__ void conv2_kernel(const float* __restrict__ w,
                             const float* __restrict__ cb, const float* __restrict__ bg,
                             const float* __restrict__ bb, const float* __restrict__ bm,
                             const float* __restrict__ bv) {
    __shared__ __align__(16) unsigned long long ws2[288 * 16];  // 36.9 KB
    __shared__ float sc[32], sh[32];
    const int tid = threadIdx.x;
    const int b = blockIdx.y;
    const int ocb = blockIdx.z * 32;

    for (int idx = tid; idx < 288 * 16; idx += 128) {
        int r = idx >> 4, ocp = idx & 15;
        ws2[idx] = packf2(w[(ocb + 2 * ocp) * 288 + r],
                          w[(ocb + 2 * ocp + 1) * 288 + r]);
    }
    if (tid < 32) {
        int oc = ocb + tid;
        float s = bg[oc] * rsqrtf(bv[oc] + 1e-5f);
        sc[tid] = s;
        sh[tid] = (cb[oc] - bm[oc]) * s + bb[oc];
    }
    __syncthreads();

    int p0 = blockIdx.x * 256 + tid;
    if (p0 >= 28 * 28) return;
    int p1 = p0 + 128;
    bool v1 = (p1 < 28 * 28);
    if (!v1) p1 = p0;

    int oh0 = p0 / 28, ow0 = p0 % 28;
    int oh1 = p1 / 28, ow1 = p1 % 28;

    // precompute per-tap offsets + validity (9 taps x 2 pixels)
    int off0[9], off1[9];
    bool ok0[9], ok1[9];
#pragma unroll
    for (int kh = 0; kh < 3; kh++)
#pragma unroll
        for (int kw = 0; kw < 3; kw++) {
            int t = kh * 3 + kw;
            int ih0 = oh0 * 2 - 1 + kh, iw0 = ow0 * 2 - 1 + kw;
            int ih1 = oh1 * 2 - 1 + kh, iw1 = ow1 * 2 - 1 + kw;
            ok0[t] = (unsigned)ih0 < 56u && (unsigned)iw0 < 56u;
            ok1[t] = (unsigned)ih1 < 56u && (unsigned)iw1 < 56u;
            off0[t] = ih0 * 56 + iw0;
            off1[t] = ih1 * 56 + iw1;
        }

    unsigned long long a0[16], a1[16];
#pragma unroll
    for (int i = 0; i < 16; i++) { a0[i] = 0ull; a1[i] = 0ull; }

    const float* inb = g_a1 + (size_t)b * 32 * 3136;
    for (int ic = 0; ic < 32; ic++) {
        const float* ip = inb + (size_t)ic * 3136;
#pragma unroll
        for (int t = 0; t < 9; t++) {
            float xv0 = ok0[t] ? __ldg(ip + off0[t]) : 0.f;
            float xv1 = ok1[t] ? __ldg(ip + off1[t]) : 0.f;
            unsigned long long x20 = bcast2(xv0), x21 = bcast2(xv1);
            const ulonglong2* wp =
                reinterpret_cast<const ulonglong2*>(&ws2[(ic * 9 + t) * 16]);
#pragma unroll
            for (int i = 0; i < 8; i++) {
                ulonglong2 wv = wp[i];
                FMA2(a0[2 * i],     x20, wv.x);
                FMA2(a0[2 * i + 1], x20, wv.y);
                FMA2(a1[2 * i],     x21, wv.x);
                FMA2(a1[2 * i + 1], x21, wv.y);
            }
        }
    }
    float* ob = g_a2 + ((size_t)b * 64 + ocb) * 784;
#pragma unroll
    for (int i = 0; i < 16; i++) {
        float y0, y1, z0, z1;
        unpack2(a0[i], y0, y1);
        unpack2(a1[i], z0, z1);
        int oc = 2 * i;
        ob[(size_t)oc * 784 + p0]       = fmaxf(y0 * sc[oc] + sh[oc], 0.f);
        ob[(size_t)(oc + 1) * 784 + p0] = fmaxf(y1 * sc[oc + 1] + sh[oc + 1], 0.f);
        if (v1) {
            ob[(size_t)oc * 784 + p1]       = fmaxf(z0 * sc[oc] + sh[oc], 0.f);
            ob[(size_t)(oc + 1) * 784 + p1] = fmaxf(z1 * sc[oc + 1] + sh[oc + 1], 0.f);
        }
    }
}

// ---------------- conv3: 64->128, 3x3, s2, p1, 28 -> 14, 2 px/thread --------
__global__ void conv3_kernel(const float* __restrict__ w,
                             const float* __restrict__ cb, const float* __restrict__ bg,
                             const float* __restrict__ bb, const float* __restrict__ bm,
                             const float* __restrict__ bv) {
    __shared__ __align__(16) unsigned long long ws2[576 * 8];  // 36.9 KB
    __shared__ float sc[16], sh[16];
    const int tid = threadIdx.x;
    const int b = blockIdx.x;
    const int ocb = blockIdx.y * 16;

    for (int idx = tid; idx < 576 * 8; idx += 128) {
        int r = idx >> 3, ocp = idx & 7;
        ws2[idx] = packf2(w[(ocb + 2 * ocp) * 576 + r],
                          w[(ocb + 2 * ocp + 1) * 576 + r]);
    }
    if (tid < 16) {
        int oc = ocb + tid;
        float s = bg[oc] * rsqrtf(bv[oc] + 1e-5f);
        sc[tid] = s;
        sh[tid] = (cb[oc] - bm[oc]) * s + bb[oc];
    }
    __syncthreads();

    if (tid >= 98) return;
    int p0 = 2 * tid, p1 = 2 * tid + 1;
    int oh0 = p0 / 14, ow0 = p0 % 14;
    int oh1 = p1 / 14, ow1 = p1 % 14;

    int off0[9], off1[9];
    bool ok0[9], ok1[9];
#pragma unroll
    for (int kh = 0; kh < 3; kh++)
#pragma unroll
        for (int kw = 0; kw < 3; kw++) {
            int t = kh * 3 + kw;
            int ih0 = oh0 * 2 - 1 + kh, iw0 = ow0 * 2 - 1 + kw;
            int ih1 = oh1 * 2 - 1 + kh, iw1 = ow1 * 2 - 1 + kw;
            ok0[t] = (unsigned)ih0 < 28u && (unsigned)iw0 < 28u;
            ok1[t] = (unsigned)ih1 < 28u && (unsigned)iw1 < 28u;
            off0[t] = ih0 * 28 + iw0;
            off1[t] = ih1 * 28 + iw1;
        }

    unsigned long long a0[8], a1[8];
#pragma unroll
    for (int i = 0; i < 8; i++) { a0[i] = 0ull; a1[i] = 0ull; }

    const float* inb = g_a2 + (size_t)b * 64 * 784;
    for (int ic = 0; ic < 64; ic++) {
        const float* ip = inb + (size_t)ic * 784;
#pragma unroll
        for (int t = 0; t < 9; t++) {
            float xv0 = ok0[t] ? __ldg(ip + off0[t]) : 0.f;
            float xv1 = ok1[t] ? __ldg(ip + off1[t]) : 0.f;
            unsigned long long x20 = bcast2(xv0), x21 = bcast2(xv1);
            const ulonglong2* wp =
                reinterpret_cast<const ulonglong2*>(&ws2[(ic * 9 + t) * 8]);
#pragma unroll
            for (int i = 0; i < 4; i++) {
                ulonglong2 wv = wp[i];
                FMA2(a0[2 * i],     x20, wv.x);
                FMA2(a0[2 * i + 1], x20, wv.y);
                FMA2(a1[2 * i],     x21, wv.x);
                FMA2(a1[2 * i + 1], x21, wv.y);
            }
        }
    }
    float* ob = g_a3 + ((size_t)b * 128 + ocb) * 196;
#pragma unroll
    for (int i = 0; i < 8; i++) {
        float y0, y1, z0, z1;
        unpack2(a0[i], y0, y1);
        unpack2(a1[i], z0, z1);
        int oc = 2 * i;
        ob[(size_t)oc * 196 + p0]       = fmaxf(y0 * sc[oc] + sh[oc], 0.f);
        ob[(size_t)(oc + 1) * 196 + p0] = fmaxf(y1 * sc[oc + 1] + sh[oc + 1], 0.f);
        ob[(size_t)oc * 196 + p1]       = fmaxf(z0 * sc[oc] + sh[oc], 0.f);
        ob[(size_t)(oc + 1) * 196 + p1] = fmaxf(z1 * sc[oc + 1] + sh[oc + 1], 0.f);
    }
}

// ---------------- adaptive avgpool (2,2): 14x14 -> 2x2 ----------------------
__global__ void pool_kernel() {
    int idx = blockIdx.x * 256 + threadIdx.x;
    if (idx >= 128 * 512) return;
    int b = idx >> 9;
    int r = idx & 511;
    int c = r >> 2;
    int ph = (r >> 1) & 1;
    int pw = r & 1;
    const float* src = g_a3 + (((size_t)b * 128 + c) * 14 + ph * 7) * 14 + pw * 7;
    float s = 0.f;
#pragma unroll
    for (int h = 0; h < 7; h++)
#pragma unroll
        for (int w = 0; w < 7; w++) s += src[h * 14 + w];
    g_feat[idx] = s * (1.f / 49.f);
}

// ---------------- head: linear->tanh, quantum circuit, MLP ------------------
__global__ void head_kernel(const float* __restrict__ pre_w, const float* __restrict__ pre_b,
                            const float* __restrict__ qw,
                            const float* __restrict__ pw1, const float* __restrict__ pb1,
                            const float* __restrict__ pw2, const float* __restrict__ pb2,
                            float* __restrict__ out) {
    __shared__ float f_s[512];
    __shared__ float ang_s[4], q_s[4], h1_s[64];
    const int tid = threadIdx.x;
    const int b = blockIdx.x;

    for (int i = tid; i < 512; i += 128) f_s[i] = g_feat[b * 512 + i];
    __syncthreads();

    int wid = tid >> 5, lane = tid & 31;
    {
        float partial = 0.f;
        const float* wr = pre_w + wid * 512;
        for (int k = lane; k < 512; k += 32) partial += f_s[k] * wr[k];
#pragma unroll
        for (int o = 16; o > 0; o >>= 1) partial += __shfl_down_sync(0xffffffffu, partial, o);
        if (lane == 0) ang_s[wid] = tanhf(partial + pre_b[wid]) * 3.14159265358979323846f;
    }
    __syncthreads();

    if (tid == 0) {
        float sr[16], si[16];
        float cq[4], sq[4];
#pragma unroll
        for (int q = 0; q < 4; q++) {
            cq[q] = cosf(0.5f * ang_s[q]);
            sq[q] = sinf(0.5f * ang_s[q]);
        }
#pragma unroll
        for (int i = 0; i < 16; i++) {
            float vv = 1.f;
#pragma unroll
            for (int q = 0; q < 4; q++) vv *= ((i >> (3 - q)) & 1) ? sq[q] : cq[q];
            sr[i] = vv;
            si[i] = 0.f;
        }
        for (int l = 0; l < 2; l++) {
            for (int q = 0; q < 4; q++) {
                const int mk = 1 << (3 - q);
                const float* qwp = qw + (l * 4 + q) * 3;
                float c, s;
                c = cosf(0.5f * qwp[0]); s = sinf(0.5f * qwp[0]);
                for (int i = 0; i < 16; i++)
                    if (!(i & mk)) {
                        int j = i | mk;
                        float r0 = sr[i], i0 = si[i], r1 = sr[j], i1 = si[j];
                        sr[i] = c * r0 + s * i1;  si[i] = c * i0 - s * r1;
                        sr[j] = c * r1 + s * i0;  si[j] = c * i1 - s * r0;
                    }
                c = cosf(0.5f * qwp[1]); s = sinf(0.5f * qwp[1]);
                for (int i = 0; i < 16; i++)
                    if (!(i & mk)) {
                        int j = i | mk;
                        float r0 = sr[i], i0 = si[i], r1 = sr[j], i1 = si[j];
                        sr[i] = c * r0 - s * r1;  si[i] = c * i0 - s * i1;
                        sr[j] = s * r0 + c * r1;  si[j] = s * i0 + c * i1;
                    }
                c = cosf(0.5f * qwp[2]); s = sinf(0.5f * qwp[2]);
                for (int i = 0; i < 16; i++) {
                    float r = sr[i], im = si[i];
                    if (i & mk) { sr[i] = c * r - s * im; si[i] = c * im + s * r; }
                    else        { sr[i] = c * r + s * im; si[i] = c * im - s * r; }
                }
            }
            for (int e = 0; e < 4; e++) {
                int cm = 1 << (3 - e);
                int tm = 1 << (3 - ((e + 1) & 3));
                for (int i = 0; i < 16; i++)
                    if ((i & cm) && !(i & tm)) {
                        int j = i | tm;
                        float t = sr[i]; sr[i] = sr[j]; sr[j] = t;
                        t = si[i]; si[i] = si[j]; si[j] = t;
                    }
            }
        }
        for (int q = 0; q < 4; q++) {
            float z = 0.f;
            for (int i = 0; i < 16; i++) {
                float pp = sr[i] * sr[i] + si[i] * si[i];
                z += ((i >> (3 - q)) & 1) ? -pp : pp;
            }
            q_s[q] = z;
        }
    }
    __syncthreads();

    if (tid < 64) {
        float h = pb1[tid];
#pragma unroll
        for (int j = 0; j < 4; j++) h += q_s[j] * pw1[tid * 4 + j];
        h1_s[tid] = fmaxf(h, 0.f);
    }
    __syncthreads();

    if (tid < 5) {
        float o = pb2[tid];
        for (int k = 0; k < 64; k++) o += h1_s[k] * pw2[tid * 64 + k];
        out[b * 5 + tid] = o;
    }
}

// ---------------- launch ----------------------------------------------------
extern "C" void kernel_launch(void* const* d_in, const int* in_sizes, int n_in,
                              void* d_out, int out_size) {
    const float* x    = (const float*)d_in[0];
    const float* c1w  = (const float*)d_in[1];
    const float* c1b  = (const float*)d_in[2];
    const float* bn1g = (const float*)d_in[3];
    const float* bn1b = (const float*)d_in[4];
    const float* bn1m = (const float*)d_in[5];
    const float* bn1v = (const float*)d_in[6];
    const float* c2w  = (const float*)d_in[7];
    const float* c2b  = (const float*)d_in[8];
    const float* bn2g = (const float*)d_in[9];
    const float* bn2b = (const float*)d_in[10];
    const float* bn2m = (const float*)d_in[11];
    const float* bn2v = (const float*)d_in[12];
    const float* c3w  = (const float*)d_in[13];
    const float* c3b  = (const float*)d_in[14];
    const float* bn3g = (const float*)d_in[15];
    const float* bn3b = (const float*)d_in[16];
    const float* bn3m = (const float*)d_in[17];
    const float* bn3v = (const float*)d_in[18];
    const float* pre_w = (const float*)d_in[19];
    const float* pre_b = (const float*)d_in[20];
    const float* qw    = (const float*)d_in[21];
    const float* pw1   = (const float*)d_in[22];
    const float* pb1   = (const float*)d_in[23];
    const float* pw2   = (const float*)d_in[24];
    const float* pb2   = (const float*)d_in[25];
    float* out = (float*)d_out;

    conv1_kernel<<<dim3(13, 128), 128>>>(x, c1w, c1b, bn1g, bn1b, bn1m, bn1v);
    conv2_kernel<<<dim3(4, 128, 2), 128>>>(c2w, c2b, bn2g, bn2b, bn2m, bn2v);
    conv3_kernel<<<dim3(128, 8), 128>>>(c3w, c3b, bn3g, bn3b, bn3m, bn3v);
    pool_kernel<<<256, 256>>>();
    head_kernel<<<128, 128>>>(pre_w, pre_b, qw, pw1, pb1, pw2, pb2, out);
}